// round 2
// baseline (speedup 1.0000x reference)
#include <cuda_runtime.h>
#include <cuda_bf16.h>

#define EPS 0.01f
#define MAX_BLOCKS 4096

__device__ float g_partials[MAX_BLOCKS];
__device__ unsigned int g_count = 0;   // reset to 0 by last block each run

__global__ void __launch_bounds__(256)
elc_fused_kernel(const float4* __restrict__ pred4,
                 const int4*   __restrict__ label4,
                 const float*  __restrict__ Wl,
                 const float*  __restrict__ label_sum,
                 const float4* __restrict__ em4,
                 int n4, int n_ls,
                 float* __restrict__ out)
{
    __shared__ float sWl[16];
    if (threadIdx.x < 16) sWl[threadIdx.x] = Wl[threadIdx.x];
    __syncthreads();

    float acc = 0.0f;
    const int stride = gridDim.x * blockDim.x;
    int i = blockIdx.x * blockDim.x + threadIdx.x;

    // 2x unrolled grid-stride loop: 6 independent LDG.128 in flight per iter
    for (; i + stride < n4; i += 2 * stride) {
        const int j = i + stride;
        float4 p0 = pred4[i];
        float4 p1 = pred4[j];
        int4   l0 = label4[i];
        int4   l1 = label4[j];
        float4 e0 = em4[i];
        float4 e1 = em4[j];
        const float w0 = sWl[(i >> 16) & 15];
        const float w1 = sWl[(j >> 16) & 15];

        float t0 = 0.0f, t1 = 0.0f;
        if (l0.x == 1) t0 += __logf(p0.x + EPS) * e0.x;
        if (l0.y == 1) t0 += __logf(p0.y + EPS) * e0.y;
        if (l0.z == 1) t0 += __logf(p0.z + EPS) * e0.z;
        if (l0.w == 1) t0 += __logf(p0.w + EPS) * e0.w;
        if (l1.x == 1) t1 += __logf(p1.x + EPS) * e1.x;
        if (l1.y == 1) t1 += __logf(p1.y + EPS) * e1.y;
        if (l1.z == 1) t1 += __logf(p1.z + EPS) * e1.z;
        if (l1.w == 1) t1 += __logf(p1.w + EPS) * e1.w;
        acc = fmaf(-w0, t0, acc);
        acc = fmaf(-w1, t1, acc);
    }
    if (i < n4) {
        float4 p = pred4[i];
        int4   l = label4[i];
        float4 e = em4[i];
        const float w = sWl[(i >> 16) & 15];
        float t = 0.0f;
        if (l.x == 1) t += __logf(p.x + EPS) * e.x;
        if (l.y == 1) t += __logf(p.y + EPS) * e.y;
        if (l.z == 1) t += __logf(p.z + EPS) * e.z;
        if (l.w == 1) t += __logf(p.w + EPS) * e.w;
        acc = fmaf(-w, t, acc);
    }

    // block reduce
    #pragma unroll
    for (int o = 16; o > 0; o >>= 1)
        acc += __shfl_xor_sync(0xffffffff, acc, o);

    __shared__ float red[8];
    const int lane = threadIdx.x & 31;
    const int wid  = threadIdx.x >> 5;
    if (lane == 0) red[wid] = acc;
    __syncthreads();
    if (wid == 0) {
        acc = (lane < (blockDim.x >> 5)) ? red[lane] : 0.0f;
        #pragma unroll
        for (int o = 4; o > 0; o >>= 1)
            acc += __shfl_xor_sync(0xffffffff, acc, o);
        if (lane == 0) g_partials[blockIdx.x] = acc;
    }

    // last-block-done protocol
    __shared__ bool s_last;
    __threadfence();
    __syncthreads();
    if (threadIdx.x == 0) {
        unsigned int old = atomicAdd(&g_count, 1u);
        s_last = (old == gridDim.x - 1);
    }
    __syncthreads();
    if (!s_last) return;

    // final reduction of per-block partials (L2-fresh loads)
    float f = 0.0f;
    for (int b = threadIdx.x; b < gridDim.x; b += blockDim.x)
        f += __ldcg(&g_partials[b]);
    #pragma unroll
    for (int o = 16; o > 0; o >>= 1)
        f += __shfl_xor_sync(0xffffffff, f, o);
    if (lane == 0) red[wid] = f;
    __syncthreads();
    if (threadIdx.x == 0) {
        float tot = 0.0f;
        #pragma unroll
        for (int w = 0; w < 8; ++w) tot += red[w];
        float s = 0.0f;
        for (int k = 0; k < n_ls; ++k) s += label_sum[k];
        out[0] = tot / s;
        g_count = 0;   // reset for next graph replay (deterministic)
    }
}

extern "C" void kernel_launch(void* const* d_in, const int* in_sizes, int n_in,
                              void* d_out, int out_size)
{
    // metadata order: pred(f32), label(i32), Wl(f32[16]), label_sum(f32[16]), existmap(f32)
    const float* pred      = (const float*)d_in[0];
    const int*   label     = (const int*)  d_in[1];
    const float* Wl        = (const float*)d_in[2];
    const float* label_sum = (const float*)d_in[3];
    const float* em        = (const float*)d_in[4];
    float* out = (float*)d_out;

    const int n_total = in_sizes[0];
    const int n4 = n_total >> 2;   // 33.55M elems, divisible by 4

    const int threads = 256;
    int blocks = 1184;  // 8 CTAs/SM * 148 SMs
    int max_blocks = (n4 + threads - 1) / threads;
    if (blocks > max_blocks) blocks = max_blocks;
    if (blocks < 1) blocks = 1;
    if (blocks > MAX_BLOCKS) blocks = MAX_BLOCKS;

    elc_fused_kernel<<<blocks, threads>>>(
        (const float4*)pred, (const int4*)label, Wl, label_sum,
        (const float4*)em, n4, in_sizes[3], out);
}

// round 3
// speedup vs baseline: 1.0034x; 1.0034x over previous
#include <cuda_runtime.h>
#include <cuda_bf16.h>

#define EPS 0.01f
#define MAX_BLOCKS 4096

__device__ float g_partials[MAX_BLOCKS];
__device__ unsigned int g_count = 0;   // reset to 0 by last block each run

__global__ void __launch_bounds__(256)
elc_fused_kernel(const float4* __restrict__ pred4,
                 const int4*   __restrict__ label4,
                 const float*  __restrict__ Wl,
                 const float*  __restrict__ label_sum,
                 const float4* __restrict__ em4,
                 int n4, int n_ls,
                 float* __restrict__ out)
{
    __shared__ float sWl[16];
    if (threadIdx.x < 16) sWl[threadIdx.x] = Wl[threadIdx.x];
    __syncthreads();

    float acc = 0.0f;
    const int stride = gridDim.x * blockDim.x;

    // plain grid-stride loop: 3 independent LDG.128 per iteration
    // (deliberately NOT unrolled: MLP_p1=3 avoids cross-CTA L1tex-queue
    //  contention at occ=8; the stream is DRAM-bound anyway)
    for (int i = blockIdx.x * blockDim.x + threadIdx.x; i < n4; i += stride) {
        float4 p = __ldcs(&pred4[i]);
        int4   l = __ldcs(&label4[i]);
        float4 e = __ldcs(&em4[i]);
        // element index = 4*i ; c = (4*i >> 18) & 15  (H*W = 2^18, C = 16)
        const float w = sWl[(i >> 16) & 15];

        float t = 0.0f;
        if (l.x == 1) t += __logf(p.x + EPS) * e.x;
        if (l.y == 1) t += __logf(p.y + EPS) * e.y;
        if (l.z == 1) t += __logf(p.z + EPS) * e.z;
        if (l.w == 1) t += __logf(p.w + EPS) * e.w;
        acc = fmaf(-w, t, acc);
    }

    // block reduce
    #pragma unroll
    for (int o = 16; o > 0; o >>= 1)
        acc += __shfl_xor_sync(0xffffffff, acc, o);

    __shared__ float red[8];
    const int lane = threadIdx.x & 31;
    const int wid  = threadIdx.x >> 5;
    if (lane == 0) red[wid] = acc;
    __syncthreads();
    if (wid == 0) {
        acc = (lane < (blockDim.x >> 5)) ? red[lane] : 0.0f;
        #pragma unroll
        for (int o = 4; o > 0; o >>= 1)
            acc += __shfl_xor_sync(0xffffffff, acc, o);
        if (lane == 0) g_partials[blockIdx.x] = acc;
    }

    // last-block-done protocol
    __shared__ bool s_last;
    __threadfence();
    __syncthreads();
    if (threadIdx.x == 0) {
        unsigned int old = atomicAdd(&g_count, 1u);
        s_last = (old == gridDim.x - 1);
    }
    __syncthreads();
    if (!s_last) return;

    // final reduction of per-block partials (L2-fresh loads)
    float f = 0.0f;
    for (int b = threadIdx.x; b < gridDim.x; b += blockDim.x)
        f += __ldcg(&g_partials[b]);
    #pragma unroll
    for (int o = 16; o > 0; o >>= 1)
        f += __shfl_xor_sync(0xffffffff, f, o);
    if (lane == 0) red[wid] = f;
    __syncthreads();
    if (threadIdx.x == 0) {
        float tot = 0.0f;
        #pragma unroll
        for (int w = 0; w < 8; ++w) tot += red[w];
        float s = 0.0f;
        for (int k = 0; k < n_ls; ++k) s += label_sum[k];
        out[0] = tot / s;
        g_count = 0;   // reset for next graph replay (deterministic)
    }
}

extern "C" void kernel_launch(void* const* d_in, const int* in_sizes, int n_in,
                              void* d_out, int out_size)
{
    // metadata order: pred(f32), label(i32), Wl(f32[16]), label_sum(f32[16]), existmap(f32)
    const float* pred      = (const float*)d_in[0];
    const int*   label     = (const int*)  d_in[1];
    const float* Wl        = (const float*)d_in[2];
    const float* label_sum = (const float*)d_in[3];
    const float* em        = (const float*)d_in[4];
    float* out = (float*)d_out;

    const int n_total = in_sizes[0];
    const int n4 = n_total >> 2;   // 33.55M elems, divisible by 4

    const int threads = 256;
    int blocks = 1184;  // 8 CTAs/SM * 148 SMs, single full wave
    int max_blocks = (n4 + threads - 1) / threads;
    if (blocks > max_blocks) blocks = max_blocks;
    if (blocks < 1) blocks = 1;
    if (blocks > MAX_BLOCKS) blocks = MAX_BLOCKS;

    elc_fused_kernel<<<blocks, threads>>>(
        (const float4*)pred, (const int4*)label, Wl, label_sum,
        (const float4*)em, n4, in_sizes[3], out);
}

// round 4
// speedup vs baseline: 1.0063x; 1.0029x over previous
#include <cuda_runtime.h>
#include <cuda_bf16.h>

#define EPS 0.01f

__device__ float g_acc = 0.0f;          // reset by last block each run
__device__ unsigned int g_count = 0;    // reset by last block each run

__global__ void __launch_bounds__(256)
elc_fused_kernel(const float4* __restrict__ pred4,
                 const int4*   __restrict__ label4,
                 const float*  __restrict__ Wl,
                 const float*  __restrict__ label_sum,
                 const float4* __restrict__ em4,
                 int n4, int n_ls,
                 float* __restrict__ out)
{
    __shared__ float sWl[16];
    if (threadIdx.x < 16) sWl[threadIdx.x] = Wl[threadIdx.x];
    __syncthreads();

    float acc = 0.0f;
    const int stride = gridDim.x * blockDim.x;

    // R1's exact loop shape: 3 independent LDG.128 per iteration, no unroll
    for (int i = blockIdx.x * blockDim.x + threadIdx.x; i < n4; i += stride) {
        float4 p = pred4[i];
        int4   l = label4[i];
        float4 e = em4[i];
        // element index = 4*i ; c = (4*i >> 18) & 15  (H*W = 2^18, C = 16)
        const float w = sWl[(i >> 16) & 15];

        float t = 0.0f;
        if (l.x == 1) t += __logf(p.x + EPS) * e.x;
        if (l.y == 1) t += __logf(p.y + EPS) * e.y;
        if (l.z == 1) t += __logf(p.z + EPS) * e.z;
        if (l.w == 1) t += __logf(p.w + EPS) * e.w;
        acc = fmaf(-w, t, acc);
    }

    // block reduce
    #pragma unroll
    for (int o = 16; o > 0; o >>= 1)
        acc += __shfl_xor_sync(0xffffffff, acc, o);

    __shared__ float red[8];
    const int lane = threadIdx.x & 31;
    const int wid  = threadIdx.x >> 5;
    if (lane == 0) red[wid] = acc;
    __syncthreads();
    if (wid == 0) {
        acc = (lane < (blockDim.x >> 5)) ? red[lane] : 0.0f;
        #pragma unroll
        for (int o = 4; o > 0; o >>= 1)
            acc += __shfl_xor_sync(0xffffffff, acc, o);
        if (lane == 0) atomicAdd(&g_acc, acc);   // device-scope atomic, no fence needed
    }
    __syncthreads();

    // arrival: ONE release-atomic per block (thread 0). The release orders this
    // thread's g_acc atomicAdd before the counter bump; the RMW chain on g_count
    // gives the final acquirer visibility of every block's add. No MEMBAR storm.
    __shared__ bool s_last;
    if (threadIdx.x == 0) {
        unsigned int old;
        asm volatile("atom.acq_rel.gpu.global.add.u32 %0, [%1], %2;"
                     : "=r"(old) : "l"(&g_count), "r"(1u) : "memory");
        s_last = (old == gridDim.x - 1);
    }
    __syncthreads();
    if (!s_last) return;

    if (threadIdx.x == 0) {
        float tot;
        asm volatile("ld.acquire.gpu.global.f32 %0, [%1];"
                     : "=f"(tot) : "l"(&g_acc) : "memory");
        float s = 0.0f;
        for (int k = 0; k < n_ls; ++k) s += label_sum[k];
        out[0] = tot / s;
        g_acc   = 0.0f;   // reset for next graph replay (flushed at kernel end)
        g_count = 0u;
    }
}

extern "C" void kernel_launch(void* const* d_in, const int* in_sizes, int n_in,
                              void* d_out, int out_size)
{
    // metadata order: pred(f32), label(i32), Wl(f32[16]), label_sum(f32[16]), existmap(f32)
    const float* pred      = (const float*)d_in[0];
    const int*   label     = (const int*)  d_in[1];
    const float* Wl        = (const float*)d_in[2];
    const float* label_sum = (const float*)d_in[3];
    const float* em        = (const float*)d_in[4];
    float* out = (float*)d_out;

    const int n_total = in_sizes[0];
    const int n4 = n_total >> 2;   // 33.55M elems, divisible by 4

    const int threads = 256;
    int blocks = 1184;  // 8 CTAs/SM * 148 SMs, single full wave
    int max_blocks = (n4 + threads - 1) / threads;
    if (blocks > max_blocks) blocks = max_blocks;
    if (blocks < 1) blocks = 1;

    elc_fused_kernel<<<blocks, threads>>>(
        (const float4*)pred, (const int4*)label, Wl, label_sum,
        (const float4*)em, n4, in_sizes[3], out);
}